// round 4
// baseline (speedup 1.0000x reference)
#include <cuda_runtime.h>

#define BB 64
#define PP 32768
#define OO 50
#define NPT 8
#define TPB_A 256
#define NBLK_LOSS (BB * PP / 256)   // 8192
#define BLK_PER_B (PP / 256)        // 128

// ---------------- scratch (static device globals; no runtime alloc) ----------------
__device__ unsigned long long g_best_packed[BB * OO]; // per (b,truth): (iou_bits<<32)|(~prior)
__device__ int   g_match[BB * PP];                    // per (b,prior): (conf<<16)|truth_idx
__device__ float g_lcneg[BB * PP];                    // lc for negatives, -1 for positives
__device__ float g_pll[NBLK_LOSS];                    // per-block smooth-L1 partials
__device__ float g_ppl[NBLK_LOSS];                    // per-block positive-lc partials
__device__ int   g_ppc[NBLK_LOSS];                    // per-block positive counts
__device__ int   g_numpos[BB];
__device__ float g_topk[BB];
__device__ float g_loss_l;
__device__ float g_loss_c_pos;

// ---------------- init ----------------
__global__ void k_init() {
    int i = blockIdx.x * blockDim.x + threadIdx.x;
    if (i < BB * OO) g_best_packed[i] = 0ull;
}

// ---------------- match: per-prior best truth + per-truth best prior ----------------
__global__ __launch_bounds__(TPB_A) void k_match(const float* __restrict__ priors,
                                                 const float* __restrict__ targets) {
    const int b = blockIdx.y;
    __shared__ float s_x0[OO], s_y0[OO], s_x1[OO], s_y1[OO], s_area[OO];
    __shared__ int s_lab[OO];
    __shared__ unsigned s_cur[OO]; // float bits of block-best iou per truth (>=0)

    const int tid = threadIdx.x;
    if (tid < OO) {
        const float* t = targets + (b * OO + tid) * 5;
        float x0 = t[0], y0 = t[1], x1 = t[2], y1 = t[3];
        s_x0[tid] = x0; s_y0[tid] = y0; s_x1[tid] = x1; s_y1[tid] = y1;
        s_area[tid] = (x1 - x0) * (y1 - y0);
        s_lab[tid] = (t[4] >= 0.f) ? 1 : 0;
        s_cur[tid] = 0u;
    }
    __syncthreads();

    const int pbase = blockIdx.x * (TPB_A * NPT);
    float px0[NPT], py0[NPT], px1[NPT], py1[NPT], pab[NPT];
    float bi[NPT], bu[NPT];
    int   bidx[NPT], pidx[NPT];
#pragma unroll
    for (int k = 0; k < NPT; k++) {
        int p = pbase + k * TPB_A + tid;
        pidx[k] = p;
        float4 pr = reinterpret_cast<const float4*>(priors)[p];
        float hw = pr.z * 0.5f, hh = pr.w * 0.5f;
        px0[k] = pr.x - hw; py0[k] = pr.y - hh;
        px1[k] = pr.x + hw; py1[k] = pr.y + hh;
        // match jax: prior area from point-form differences (rounding-faithful)
        pab[k] = (px1[k] - px0[k]) * (py1[k] - py0[k]);
        bi[k] = 0.f; bu[k] = 1.f; bidx[k] = 0;
    }

    const int wid = tid >> 5;
    for (int tt = 0; tt < OO; tt++) {
        int t = tt + wid * 6; if (t >= OO) t -= OO; // rotate start per warp
        const float tx0 = s_x0[t], ty0 = s_y0[t], tx1 = s_x1[t], ty1 = s_y1[t], ta = s_area[t];
        float cur = __uint_as_float(s_cur[t]);
#pragma unroll
        for (int k = 0; k < NPT; k++) {
            float w = fminf(px1[k], tx1) - fmaxf(px0[k], tx0);
            float h = fminf(py1[k], ty1) - fmaxf(py0[k], ty0);
            w = fmaxf(w, 0.f); h = fmaxf(h, 0.f);
            float inter = w * h;
            float uni = ta + pab[k] - inter;
            // per-prior best truth: strict > keeps first (lower t wins ties).
            // NOTE: t iterates rotated, so convert to a first-index-compatible rule:
            // track exact best; ties in cross-mult resolved by smaller t.
            float lhs = inter * bu[k], rhs = bi[k] * uni;
            if (lhs > rhs || (lhs == rhs && t < bidx[k] && inter > 0.f)) {
                bi[k] = inter; bu[k] = uni; bidx[k] = t;
            }
            // per-truth best prior (rare slow path behind smem prefilter)
            if (inter >= cur * uni && inter > 0.f) {
                float iou = inter / uni;
                unsigned bits = __float_as_uint(iou);
                unsigned old = atomicMax(&s_cur[t], bits);
                cur = __uint_as_float(old > bits ? old : bits);
                unsigned long long key =
                    ((unsigned long long)bits << 32) | (unsigned)(~pidx[k]);
                atomicMax(&g_best_packed[b * OO + t], key); // int max: order-invariant
            }
        }
    }

#pragma unroll
    for (int k = 0; k < NPT; k++) {
        int conf = (2.f * bi[k] >= bu[k] && bi[k] > 0.f) ? s_lab[bidx[k]] : 0; // iou >= 0.5
        g_match[b * PP + pidx[k]] = (conf << 16) | bidx[k];
    }
}

// ---------------- override: force each truth's best prior (last-j-wins) ----------------
__global__ void k_override(const float* __restrict__ targets) {
    int b = threadIdx.x;
    if (b >= BB) return;
    for (int j = 0; j < OO; j++) {
        unsigned long long pk = g_best_packed[b * OO + j];
        int p = (pk == 0ull) ? 0 : (int)(~(unsigned)(pk & 0xFFFFFFFFull));
        int lab = (targets[(b * OO + j) * 5 + 4] >= 0.f) ? 1 : 0;
        g_match[b * PP + p] = (lab << 16) | j;
    }
}

// ---------------- per-prior losses: lc, smooth-L1 on positives, block partials ----------------
__global__ __launch_bounds__(256) void k_loss(const float* __restrict__ arm_loc,
                                              const float* __restrict__ arm_conf,
                                              const float* __restrict__ priors,
                                              const float* __restrict__ targets) {
    const int gid = blockIdx.x * 256 + threadIdx.x;
    const int b = gid >> 15;
    const int p = gid & (PP - 1);

    const int m = g_match[gid];
    const int conf = m >> 16;
    const int idx = m & 0xFFFF;

    float2 c = reinterpret_cast<const float2*>(arm_conf)[gid];
    float mx = fmaxf(c.x, c.y);
    float lse = mx + __logf(__expf(c.x - mx) + __expf(c.y - mx));
    float picked = conf ? c.y : c.x;
    float lc = lse - picked;
    bool pos = conf > 0;

    g_lcneg[gid] = pos ? -1.0f : lc;

    float ll = 0.f;
    float plc = pos ? lc : 0.f;
    if (pos) {
        float4 pr = reinterpret_cast<const float4*>(priors)[p];
        const float* t = targets + (b * OO + idx) * 5;
        float tx0 = t[0], ty0 = t[1], tx1 = t[2], ty1 = t[3];
        float gcx = ((tx0 + tx1) * 0.5f - pr.x) / (0.1f * pr.z);
        float gcy = ((ty0 + ty1) * 0.5f - pr.y) / (0.1f * pr.w);
        float gw = __logf((tx1 - tx0) / pr.z) * 5.0f; // /VAR[1]=0.2
        float gh = __logf((ty1 - ty0) / pr.w) * 5.0f;
        float4 l = reinterpret_cast<const float4*>(arm_loc)[gid];
        float d, ad;
        d = l.x - gcx; ad = fabsf(d); ll += (ad < 1.f) ? 0.5f * d * d : ad - 0.5f;
        d = l.y - gcy; ad = fabsf(d); ll += (ad < 1.f) ? 0.5f * d * d : ad - 0.5f;
        d = l.z - gw;  ad = fabsf(d); ll += (ad < 1.f) ? 0.5f * d * d : ad - 0.5f;
        d = l.w - gh;  ad = fabsf(d); ll += (ad < 1.f) ? 0.5f * d * d : ad - 0.5f;
    }

    // deterministic block reduction (fixed tree)
    for (int o = 16; o > 0; o >>= 1) {
        ll  += __shfl_down_sync(0xFFFFFFFFu, ll, o);
        plc += __shfl_down_sync(0xFFFFFFFFu, plc, o);
    }
    int pc = __popc(__ballot_sync(0xFFFFFFFFu, pos));

    __shared__ float s_ll[8], s_plc[8];
    __shared__ int s_pc[8];
    int lane = threadIdx.x & 31, w = threadIdx.x >> 5;
    if (lane == 0) { s_ll[w] = ll; s_plc[w] = plc; s_pc[w] = pc; }
    __syncthreads();
    if (threadIdx.x == 0) {
        float L = 0.f, Pl = 0.f; int C = 0;
        for (int i = 0; i < 8; i++) { L += s_ll[i]; Pl += s_plc[i]; C += s_pc[i]; }
        g_pll[blockIdx.x] = L;
        g_ppl[blockIdx.x] = Pl;
        g_ppc[blockIdx.x] = C;
    }
}

// ---------------- deterministic partial reduction ----------------
__global__ __launch_bounds__(128) void k_reduce() {
    const int b = blockIdx.x, tid = threadIdx.x;
    // per-batch numpos from this batch's 128 block partials
    int c = g_ppc[b * BLK_PER_B + tid];
    __shared__ int s_c[128];
    s_c[tid] = c;
    __syncthreads();
    for (int o = 64; o > 0; o >>= 1) {
        if (tid < o) s_c[tid] += s_c[tid + o];
        __syncthreads();
    }
    if (tid == 0) g_numpos[b] = s_c[0];

    if (b == 0) {
        // global loss_l and positive-lc sums over all 8192 partials, fixed order
        float L = 0.f, Pl = 0.f;
        for (int i = tid; i < NBLK_LOSS; i += 128) { L += g_pll[i]; Pl += g_ppl[i]; }
        __shared__ float s_l[128], s_p[128];
        s_l[tid] = L; s_p[tid] = Pl;
        __syncthreads();
        for (int o = 64; o > 0; o >>= 1) {
            if (tid < o) { s_l[tid] += s_l[tid + o]; s_p[tid] += s_p[tid + o]; }
            __syncthreads();
        }
        if (tid == 0) { g_loss_l = s_l[0]; g_loss_c_pos = s_p[0]; }
    }
}

// ---------------- hard-negative mining: exact top-k sum via radix select ----------------
__global__ __launch_bounds__(1024) void k_topk() {
    extern __shared__ float s_lc[]; // PP floats
    __shared__ int s_cnt[256];
    __shared__ float s_rsum[32];
    __shared__ int s_rcnt[32];
    __shared__ unsigned sh_prefix;
    __shared__ int sh_krem, sh_k;

    const int b = blockIdx.x, tid = threadIdx.x, lane = tid & 31, w = tid >> 5;
    const float* src = g_lcneg + b * PP;
    for (int i = tid; i < PP; i += 1024) s_lc[i] = src[i];
    if (tid == 0) {
        long long k = 3ll * (long long)g_numpos[b];
        if (k > PP - 1) k = PP - 1;
        sh_k = (int)k; sh_krem = (int)k; sh_prefix = 0u;
    }
    __syncthreads();

    for (int pass = 0; pass < 4; pass++) {
        const int shift = 24 - 8 * pass;
        if (tid < 256) s_cnt[tid] = 0;
        __syncthreads();
        const unsigned pf = sh_prefix;
        const unsigned himask = (pass == 0) ? 0u : (0xFFFFFFFFu << (shift + 8));
        for (int i = tid; i < PP; i += 1024) {
            float v = s_lc[i];
            unsigned bits = __float_as_uint(v);
            bool ok = (v >= 0.f) && ((bits & himask) == pf);
            int byte = ok ? (int)((bits >> shift) & 255u) : 300;
            unsigned mm = __match_any_sync(0xFFFFFFFFu, byte);
            if (ok && ((__ffs(mm) - 1) == lane)) atomicAdd(&s_cnt[byte], __popc(mm));
        }
        __syncthreads();
        if (tid == 0) {
            if (pass == 0) { // clamp k to number of negative candidates
                int tot = 0;
                for (int j = 0; j < 256; j++) tot += s_cnt[j];
                if (sh_krem > tot) { sh_krem = tot; sh_k = tot; }
            }
            int kr = sh_krem;
            if (kr > 0) {
                int c = 0, sel = 0;
                for (int j = 255; j >= 0; j--) {
                    if (c + s_cnt[j] >= kr) { sel = j; break; }
                    c += s_cnt[j];
                }
                sh_prefix |= ((unsigned)sel) << shift;
                sh_krem = kr - c;
            }
        }
        __syncthreads();
    }

    // deterministic: fixed strided traversal + fixed tree reduce
    const float T = __uint_as_float(sh_prefix);
    float sg = 0.f; int cg = 0;
    for (int i = tid; i < PP; i += 1024) {
        float v = s_lc[i];
        if (v > T) { sg += v; cg++; }
    }
    for (int o = 16; o > 0; o >>= 1) {
        sg += __shfl_down_sync(0xFFFFFFFFu, sg, o);
        cg += __shfl_down_sync(0xFFFFFFFFu, cg, o);
    }
    if (lane == 0) { s_rsum[w] = sg; s_rcnt[w] = cg; }
    __syncthreads();
    if (tid == 0) {
        float S = 0.f; int C = 0;
        for (int i = 0; i < 32; i++) { S += s_rsum[i]; C += s_rcnt[i]; }
        g_topk[b] = (sh_k > 0) ? (S + (float)(sh_k - C) * T) : 0.f;
    }
}

// ---------------- finalize (single thread, fixed order -> deterministic) ----------------
__global__ void k_final(float* __restrict__ out) {
    int N = 0;
    for (int bb = 0; bb < BB; bb++) N += g_numpos[bb];
    float tk = 0.f;
    for (int bb = 0; bb < BB; bb++) tk += g_topk[bb];
    float fn = (float)N;
    out[0] = g_loss_l / fn;
    out[1] = (g_loss_c_pos + tk) / fn;
}

extern "C" void kernel_launch(void* const* d_in, const int* in_sizes, int n_in,
                              void* d_out, int out_size) {
    const float* arm_loc  = (const float*)d_in[0];
    const float* arm_conf = (const float*)d_in[1];
    const float* priors   = (const float*)d_in[4];
    const float* targets  = (const float*)d_in[5];
    float* out = (float*)d_out;

    (void)in_sizes; (void)n_in; (void)out_size;

    static int smem_set = 0;
    if (!smem_set) {
        cudaFuncSetAttribute(k_topk, cudaFuncAttributeMaxDynamicSharedMemorySize, PP * 4);
        smem_set = 1;
    }

    k_init<<<(BB * OO + 255) / 256, 256>>>();
    k_match<<<dim3(PP / (TPB_A * NPT), BB), TPB_A>>>(priors, targets);
    k_override<<<1, 64>>>(targets);
    k_loss<<<NBLK_LOSS, 256>>>(arm_loc, arm_conf, priors, targets);
    k_reduce<<<BB, 128>>>();
    k_topk<<<BB, 1024, PP * 4>>>();
    k_final<<<1, 1>>>(out);
}

// round 5
// speedup vs baseline: 1.1305x; 1.1305x over previous
#include <cuda_runtime.h>

#define BB 64
#define PP 32768
#define OO 50
#define NPT 8
#define TPB_A 256
#define NBLK_LOSS (BB * PP / 256)   // 8192
#define BLK_PER_B (PP / 256)        // 128

// ---------------- scratch (static device globals; no runtime alloc) ----------------
__device__ unsigned long long g_best_packed[BB * OO]; // per (b,truth): (iou_bits<<32)|(~prior)
__device__ int   g_match[BB * PP];                    // per (b,prior): (conf<<16)|truth_idx
__device__ float g_lcneg[BB * PP];                    // lc for negatives, -1 for positives
__device__ float g_pll[NBLK_LOSS];                    // per-block smooth-L1 partials
__device__ float g_ppl[NBLK_LOSS];                    // per-block positive-lc partials
__device__ int   g_ppc[NBLK_LOSS];                    // per-block positive counts
__device__ int   g_numpos[BB];
__device__ float g_topk[BB];
__device__ float g_loss_l;
__device__ float g_loss_c_pos;

// ---------------- init / pad ----------------
__global__ void k_init() {
    int i = blockIdx.x * blockDim.x + threadIdx.x;
    if (i < BB * OO) g_best_packed[i] = 0ull;
}
__global__ void k_pad() {} // launch-order shim so ncu -s 5 captures k_match

// ---------------- match: per-prior best truth + per-truth best prior ----------------
__global__ __launch_bounds__(TPB_A) void k_match(const float* __restrict__ priors,
                                                 const float* __restrict__ targets) {
    const int b = blockIdx.y;
    __shared__ float s_x0[OO], s_y0[OO], s_x1[OO], s_y1[OO], s_area[OO];
    __shared__ int s_lab[OO];
    __shared__ unsigned s_cur[OO]; // float bits of block-best iou per truth (>= 1e-30)

    const int tid = threadIdx.x;
    if (tid < OO) {
        const float* t = targets + (b * OO + tid) * 5;
        float x0 = t[0], y0 = t[1], x1 = t[2], y1 = t[3];
        s_x0[tid] = x0; s_y0[tid] = y0; s_x1[tid] = x1; s_y1[tid] = y1;
        s_area[tid] = (x1 - x0) * (y1 - y0);
        s_lab[tid] = (t[4] >= 0.f) ? 1 : 0;
        s_cur[tid] = __float_as_uint(1e-30f); // tiny positive: prunes inter==0 for free
    }
    __syncthreads();

    const int pbase = blockIdx.x * (TPB_A * NPT);
    float px0[NPT], py0[NPT], px1[NPT], py1[NPT], pab[NPT];
    float bi[NPT], bu[NPT];
    int   bidx[NPT];
#pragma unroll
    for (int k = 0; k < NPT; k++) {
        int p = pbase + k * TPB_A + tid;
        float4 pr = reinterpret_cast<const float4*>(priors)[p];
        float hw = pr.z * 0.5f, hh = pr.w * 0.5f;
        px0[k] = pr.x - hw; py0[k] = pr.y - hh;
        px1[k] = pr.x + hw; py1[k] = pr.y + hh;
        // match jax: prior area from point-form differences (rounding-faithful)
        pab[k] = (px1[k] - px0[k]) * (py1[k] - py0[k]);
        bi[k] = 0.f; bu[k] = 1.f; bidx[k] = 0;
    }

    const int wid = tid >> 5;
    for (int tt = 0; tt < OO; tt++) {
        int t = tt + wid * 6; if (t >= OO) t -= OO; // rotate start per warp
        const float tx0 = s_x0[t], ty0 = s_y0[t], tx1 = s_x1[t], ty1 = s_y1[t], ta = s_area[t];
        float cur = __uint_as_float(s_cur[t]); // plain LDS; staleness OK (pruning only)
#pragma unroll
        for (int k = 0; k < NPT; k++) {
            float w = fminf(px1[k], tx1) - fmaxf(px0[k], tx0);
            float h = fminf(py1[k], ty1) - fmaxf(py0[k], ty0);
            float inter = fmaxf(w, 0.f) * fmaxf(h, 0.f);
            float uni = (ta + pab[k]) - inter;
            // per-prior best truth (cross-mult, strict >; first-seen wins on exact tie)
            if (fmaf(inter, bu[k], -(bi[k] * uni)) > 0.f) {
                bi[k] = inter; bu[k] = uni; bidx[k] = t;
            }
            // per-truth best prior: warp-aggregated rare path
            bool take = inter >= cur * uni;
            if (__any_sync(0xFFFFFFFFu, take)) { // warp-uniform branch
                float iou = inter / uni;         // IEEE div; only on rare path
                unsigned long long key = 0ull;
                if (take) {
                    int p = pbase + k * TPB_A + tid;
                    key = ((unsigned long long)__float_as_uint(iou) << 32)
                        | (unsigned)(~p); // tiebreak: lowest prior index
                }
#pragma unroll
                for (int o = 16; o > 0; o >>= 1) {
                    unsigned long long other = __shfl_xor_sync(0xFFFFFFFFu, key, o);
                    if (other > key) key = other;
                }
                float wmax = __uint_as_float((unsigned)(key >> 32));
                cur = fmaxf(cur, wmax);
                if ((tid & 31) == 0 && key != 0ull) {
                    atomicMax(&s_cur[t], __float_as_uint(wmax));
                    atomicMax(&g_best_packed[b * OO + t], key); // int max: order-invariant
                }
            }
        }
    }

#pragma unroll
    for (int k = 0; k < NPT; k++) {
        int conf = (2.f * bi[k] >= bu[k] && bi[k] > 0.f) ? s_lab[bidx[k]] : 0; // iou >= 0.5
        g_match[b * PP + pbase + k * TPB_A + tid] = (conf << 16) | bidx[k];
    }
}

// ---------------- override: force each truth's best prior (last-j-wins) ----------------
__global__ void k_override(const float* __restrict__ targets) {
    int b = threadIdx.x;
    if (b >= BB) return;
    for (int j = 0; j < OO; j++) {
        unsigned long long pk = g_best_packed[b * OO + j];
        int p = (pk == 0ull) ? 0 : (int)(~(unsigned)(pk & 0xFFFFFFFFull));
        int lab = (targets[(b * OO + j) * 5 + 4] >= 0.f) ? 1 : 0;
        g_match[b * PP + p] = (lab << 16) | j;
    }
}

// ---------------- per-prior losses: lc, smooth-L1 on positives, block partials ----------------
__global__ __launch_bounds__(256) void k_loss(const float* __restrict__ arm_loc,
                                              const float* __restrict__ arm_conf,
                                              const float* __restrict__ priors,
                                              const float* __restrict__ targets) {
    const int gid = blockIdx.x * 256 + threadIdx.x;
    const int b = gid >> 15;
    const int p = gid & (PP - 1);

    const int m = g_match[gid];
    const int conf = m >> 16;
    const int idx = m & 0xFFFF;

    float2 c = reinterpret_cast<const float2*>(arm_conf)[gid];
    float mx = fmaxf(c.x, c.y);
    float lse = mx + __logf(__expf(c.x - mx) + __expf(c.y - mx));
    float picked = conf ? c.y : c.x;
    float lc = lse - picked;
    bool pos = conf > 0;

    g_lcneg[gid] = pos ? -1.0f : lc;

    float ll = 0.f;
    float plc = pos ? lc : 0.f;
    if (pos) {
        float4 pr = reinterpret_cast<const float4*>(priors)[p];
        const float* t = targets + (b * OO + idx) * 5;
        float tx0 = t[0], ty0 = t[1], tx1 = t[2], ty1 = t[3];
        float gcx = ((tx0 + tx1) * 0.5f - pr.x) / (0.1f * pr.z);
        float gcy = ((ty0 + ty1) * 0.5f - pr.y) / (0.1f * pr.w);
        float gw = __logf((tx1 - tx0) / pr.z) * 5.0f; // /VAR[1]=0.2
        float gh = __logf((ty1 - ty0) / pr.w) * 5.0f;
        float4 l = reinterpret_cast<const float4*>(arm_loc)[gid];
        float d, ad;
        d = l.x - gcx; ad = fabsf(d); ll += (ad < 1.f) ? 0.5f * d * d : ad - 0.5f;
        d = l.y - gcy; ad = fabsf(d); ll += (ad < 1.f) ? 0.5f * d * d : ad - 0.5f;
        d = l.z - gw;  ad = fabsf(d); ll += (ad < 1.f) ? 0.5f * d * d : ad - 0.5f;
        d = l.w - gh;  ad = fabsf(d); ll += (ad < 1.f) ? 0.5f * d * d : ad - 0.5f;
    }

    // deterministic block reduction (fixed tree)
    for (int o = 16; o > 0; o >>= 1) {
        ll  += __shfl_down_sync(0xFFFFFFFFu, ll, o);
        plc += __shfl_down_sync(0xFFFFFFFFu, plc, o);
    }
    int pc = __popc(__ballot_sync(0xFFFFFFFFu, pos));

    __shared__ float s_ll[8], s_plc[8];
    __shared__ int s_pc[8];
    int lane = threadIdx.x & 31, w = threadIdx.x >> 5;
    if (lane == 0) { s_ll[w] = ll; s_plc[w] = plc; s_pc[w] = pc; }
    __syncthreads();
    if (threadIdx.x == 0) {
        float L = 0.f, Pl = 0.f; int C = 0;
        for (int i = 0; i < 8; i++) { L += s_ll[i]; Pl += s_plc[i]; C += s_pc[i]; }
        g_pll[blockIdx.x] = L;
        g_ppl[blockIdx.x] = Pl;
        g_ppc[blockIdx.x] = C;
    }
}

// ---------------- deterministic partial reduction ----------------
__global__ __launch_bounds__(128) void k_reduce() {
    const int b = blockIdx.x, tid = threadIdx.x;
    int c = g_ppc[b * BLK_PER_B + tid];
    __shared__ int s_c[128];
    s_c[tid] = c;
    __syncthreads();
    for (int o = 64; o > 0; o >>= 1) {
        if (tid < o) s_c[tid] += s_c[tid + o];
        __syncthreads();
    }
    if (tid == 0) g_numpos[b] = s_c[0];

    if (b == 0) {
        float L = 0.f, Pl = 0.f;
        for (int i = tid; i < NBLK_LOSS; i += 128) { L += g_pll[i]; Pl += g_ppl[i]; }
        __shared__ float s_l[128], s_p[128];
        s_l[tid] = L; s_p[tid] = Pl;
        __syncthreads();
        for (int o = 64; o > 0; o >>= 1) {
            if (tid < o) { s_l[tid] += s_l[tid + o]; s_p[tid] += s_p[tid + o]; }
            __syncthreads();
        }
        if (tid == 0) { g_loss_l = s_l[0]; g_loss_c_pos = s_p[0]; }
    }
}

// ---------------- hard-negative mining: exact top-k sum via radix select ----------------
__global__ __launch_bounds__(1024) void k_topk() {
    extern __shared__ float s_lc[]; // PP floats
    __shared__ int s_cnt[256];
    __shared__ float s_rsum[32];
    __shared__ int s_rcnt[32];
    __shared__ unsigned sh_prefix;
    __shared__ int sh_krem, sh_k;

    const int b = blockIdx.x, tid = threadIdx.x, lane = tid & 31, w = tid >> 5;
    const float* src = g_lcneg + b * PP;
    for (int i = tid; i < PP; i += 1024) s_lc[i] = src[i];
    if (tid == 0) {
        long long k = 3ll * (long long)g_numpos[b];
        if (k > PP - 1) k = PP - 1;
        sh_k = (int)k; sh_krem = (int)k; sh_prefix = 0u;
    }
    __syncthreads();

    for (int pass = 0; pass < 4; pass++) {
        const int shift = 24 - 8 * pass;
        if (tid < 256) s_cnt[tid] = 0;
        __syncthreads();
        const unsigned pf = sh_prefix;
        const unsigned himask = (pass == 0) ? 0u : (0xFFFFFFFFu << (shift + 8));
        for (int i = tid; i < PP; i += 1024) {
            float v = s_lc[i];
            unsigned bits = __float_as_uint(v);
            bool ok = (v >= 0.f) && ((bits & himask) == pf);
            int byte = ok ? (int)((bits >> shift) & 255u) : 300;
            unsigned mm = __match_any_sync(0xFFFFFFFFu, byte);
            if (ok && ((__ffs(mm) - 1) == lane)) atomicAdd(&s_cnt[byte], __popc(mm));
        }
        __syncthreads();
        if (tid == 0) {
            if (pass == 0) { // clamp k to number of negative candidates
                int tot = 0;
                for (int j = 0; j < 256; j++) tot += s_cnt[j];
                if (sh_krem > tot) { sh_krem = tot; sh_k = tot; }
            }
            int kr = sh_krem;
            if (kr > 0) {
                int c = 0, sel = 0;
                for (int j = 255; j >= 0; j--) {
                    if (c + s_cnt[j] >= kr) { sel = j; break; }
                    c += s_cnt[j];
                }
                sh_prefix |= ((unsigned)sel) << shift;
                sh_krem = kr - c;
            }
        }
        __syncthreads();
    }

    const float T = __uint_as_float(sh_prefix);
    float sg = 0.f; int cg = 0;
    for (int i = tid; i < PP; i += 1024) {
        float v = s_lc[i];
        if (v > T) { sg += v; cg++; }
    }
    for (int o = 16; o > 0; o >>= 1) {
        sg += __shfl_down_sync(0xFFFFFFFFu, sg, o);
        cg += __shfl_down_sync(0xFFFFFFFFu, cg, o);
    }
    if (lane == 0) { s_rsum[w] = sg; s_rcnt[w] = cg; }
    __syncthreads();
    if (tid == 0) {
        float S = 0.f; int C = 0;
        for (int i = 0; i < 32; i++) { S += s_rsum[i]; C += s_rcnt[i]; }
        g_topk[b] = (sh_k > 0) ? (S + (float)(sh_k - C) * T) : 0.f;
    }
}

// ---------------- finalize (single thread, fixed order -> deterministic) ----------------
__global__ void k_final(float* __restrict__ out) {
    int N = 0;
    for (int bb = 0; bb < BB; bb++) N += g_numpos[bb];
    float tk = 0.f;
    for (int bb = 0; bb < BB; bb++) tk += g_topk[bb];
    float fn = (float)N;
    out[0] = g_loss_l / fn;
    out[1] = (g_loss_c_pos + tk) / fn;
}

extern "C" void kernel_launch(void* const* d_in, const int* in_sizes, int n_in,
                              void* d_out, int out_size) {
    const float* arm_loc  = (const float*)d_in[0];
    const float* arm_conf = (const float*)d_in[1];
    const float* priors   = (const float*)d_in[4];
    const float* targets  = (const float*)d_in[5];
    float* out = (float*)d_out;

    (void)in_sizes; (void)n_in; (void)out_size;

    static int smem_set = 0;
    if (!smem_set) {
        cudaFuncSetAttribute(k_topk, cudaFuncAttributeMaxDynamicSharedMemorySize, PP * 4);
        smem_set = 1;
    }

    k_init<<<(BB * OO + 255) / 256, 256>>>();
    k_pad<<<1, 32>>>();
    k_pad<<<1, 32>>>();
    k_match<<<dim3(PP / (TPB_A * NPT), BB), TPB_A>>>(priors, targets);
    k_override<<<1, 64>>>(targets);
    k_loss<<<NBLK_LOSS, 256>>>(arm_loc, arm_conf, priors, targets);
    k_reduce<<<BB, 128>>>();
    k_topk<<<BB, 1024, PP * 4>>>();
    k_final<<<1, 1>>>(out);
}

// round 7
// speedup vs baseline: 1.3136x; 1.1620x over previous
#include <cuda_runtime.h>

#define BB 64
#define PP 32768
#define OO 50
#define NPT 8
#define TPB_A 256
#define NBLK_LOSS (BB * PP / 256)   // 8192
#define BLK_PER_B (PP / 256)        // 128

// ---------------- scratch (static device globals; no runtime alloc) ----------------
__device__ unsigned long long g_best_packed[BB * OO]; // per (b,truth): (iou_bits<<32)|(~prior)
__device__ int   g_match[BB * PP];                    // normal: (conf<<16)|t ; override: (1<<30)|(j<<16)|lab
__device__ float g_lcneg[BB * PP];                    // lc for negatives, -1 for positives
__device__ float g_pll[NBLK_LOSS];                    // per-block smooth-L1 partials
__device__ float g_ppl[NBLK_LOSS];                    // per-block positive-lc partials
__device__ int   g_ppc[NBLK_LOSS];                    // per-block positive counts
__device__ int   g_numpos[BB];
__device__ float g_topk[BB];
__device__ float g_loss_l;
__device__ float g_loss_c_pos;

// ---------------- init / pad ----------------
__global__ void k_init() {
    int i = blockIdx.x * blockDim.x + threadIdx.x;
    if (i < BB * OO) g_best_packed[i] = 0ull;
}
__global__ void k_pad() {} // launch-order shim so ncu (4th launch) captures k_match

// ---------------- match: per-prior best truth + per-truth best prior ----------------
__global__ __launch_bounds__(TPB_A, 3) void k_match(const float* __restrict__ priors,
                                                    const float* __restrict__ targets) {
    const int b = blockIdx.y;
    __shared__ float s_x0[OO], s_y0[OO], s_x1[OO], s_y1[OO], s_area[OO];
    __shared__ int s_lab[OO];
    __shared__ unsigned s_cur[OO]; // float bits of block-best iou per truth (>= 1e-30)

    const int tid = threadIdx.x;
    if (tid < OO) {
        const float* t = targets + (b * OO + tid) * 5;
        float x0 = t[0], y0 = t[1], x1 = t[2], y1 = t[3];
        s_x0[tid] = x0; s_y0[tid] = y0; s_x1[tid] = x1; s_y1[tid] = y1;
        s_area[tid] = (x1 - x0) * (y1 - y0);
        s_lab[tid] = (t[4] >= 0.f) ? 1 : 0;
        s_cur[tid] = __float_as_uint(1e-30f); // tiny positive: prunes inter==0 for free
    }
    __syncthreads();

    const int pbase = blockIdx.x * (TPB_A * NPT);
    float px0[NPT], py0[NPT], px1[NPT], py1[NPT], pab[NPT];
    float bi[NPT], bu[NPT];
    int   bidx[NPT];
#pragma unroll
    for (int k = 0; k < NPT; k++) {
        int p = pbase + k * TPB_A + tid;
        float4 pr = reinterpret_cast<const float4*>(priors)[p];
        float hw = pr.z * 0.5f, hh = pr.w * 0.5f;
        px0[k] = pr.x - hw; py0[k] = pr.y - hh;
        px1[k] = pr.x + hw; py1[k] = pr.y + hh;
        // match jax: prior area from point-form differences (rounding-faithful)
        pab[k] = (px1[k] - px0[k]) * (py1[k] - py0[k]);
        bi[k] = 0.f; bu[k] = 1.f; bidx[k] = 0;
    }

    const int wid = tid >> 5;
    for (int tt = 0; tt < OO; tt++) {
        int t = tt + wid * 6; if (t >= OO) t -= OO; // rotate start per warp
        const float tx0 = s_x0[t], ty0 = s_y0[t], tx1 = s_x1[t], ty1 = s_y1[t], ta = s_area[t];
        float cur = __uint_as_float(s_cur[t]); // plain LDS; staleness OK (pruning only)
        float slack = -1.f;
#pragma unroll
        for (int k = 0; k < NPT; k++) {
            float w = fminf(px1[k], tx1) - fmaxf(px0[k], tx0);
            float h = fminf(py1[k], ty1) - fmaxf(py0[k], ty0);
            float inter = fmaxf(w, 0.f) * fmaxf(h, 0.f);
            float uni = (ta + pab[k]) - inter;
            // per-prior best truth (cross-mult, strict >; first-seen wins on tie)
            if (inter * bu[k] > bi[k] * uni) {
                bi[k] = inter; bu[k] = uni; bidx[k] = t;
            }
            // prefilter accumulation only (no branch, no vote per pair)
            slack = fmaxf(slack, fmaf(-cur, uni, inter)); // >=0 iff inter >= cur*uni
        }
        // per-truth best prior: rare, warp-uniform slow path (once per t)
        if (__any_sync(0xFFFFFFFFu, slack >= 0.f)) {
            unsigned long long key = 0ull;
#pragma unroll
            for (int k = 0; k < NPT; k++) {
                float w = fminf(px1[k], tx1) - fmaxf(px0[k], tx0);
                float h = fminf(py1[k], ty1) - fmaxf(py0[k], ty0);
                float inter = fmaxf(w, 0.f) * fmaxf(h, 0.f);
                float uni = (ta + pab[k]) - inter;
                if (inter >= cur * uni) {
                    float iou = inter / uni; // IEEE div, matches ref exactly
                    unsigned long long kk =
                        ((unsigned long long)__float_as_uint(iou) << 32)
                        | (unsigned)(~(pbase + k * TPB_A + tid)); // tiebreak: lowest prior
                    if (kk > key) key = kk;
                }
            }
#pragma unroll
            for (int o = 16; o > 0; o >>= 1) {
                unsigned long long other = __shfl_xor_sync(0xFFFFFFFFu, key, o);
                if (other > key) key = other;
            }
            if ((tid & 31) == 0 && key != 0ull) {
                atomicMax(&s_cur[t], (unsigned)(key >> 32));
                atomicMax(&g_best_packed[b * OO + t], key); // int max: order-invariant
            }
        }
    }

#pragma unroll
    for (int k = 0; k < NPT; k++) {
        int conf = (2.f * bi[k] >= bu[k]) ? s_lab[bidx[k]] : 0; // iou >= 0.5 (bi>0 implied)
        g_match[b * PP + pbase + k * TPB_A + tid] = (conf << 16) | bidx[k];
    }
}

// ---------------- override: force each truth's best prior (last-j-wins via j-dominant max) --------
__global__ void k_override(const float* __restrict__ targets) {
    int i = blockIdx.x * blockDim.x + threadIdx.x;
    if (i >= BB * OO) return;
    int b = i / OO, j = i - b * OO;
    unsigned long long pk = g_best_packed[i];
    int p = (pk == 0ull) ? 0 : (int)(~(unsigned)(pk & 0xFFFFFFFFull));
    int lab = (targets[i * 5 + 4] >= 0.f) ? 1 : 0;
    // bit30 tag beats any normal match; among overrides larger j wins (= last-j-wins)
    atomicMax(&g_match[b * PP + p], (1 << 30) | (j << 16) | lab);
}

// ---------------- per-prior losses: lc, smooth-L1 on positives, block partials ----------------
__global__ __launch_bounds__(256) void k_loss(const float* __restrict__ arm_loc,
                                              const float* __restrict__ arm_conf,
                                              const float* __restrict__ priors,
                                              const float* __restrict__ targets) {
    const int gid = blockIdx.x * 256 + threadIdx.x;
    const int b = gid >> 15;
    const int p = gid & (PP - 1);

    const int m = g_match[gid];
    int conf, idx;
    if (m & (1 << 30)) { idx = (m >> 16) & 0x3FFF; conf = m & 1; }
    else               { conf = m >> 16;           idx = m & 0xFFFF; }

    float2 c = reinterpret_cast<const float2*>(arm_conf)[gid];
    // lse - picked = softplus(other - picked): 2 MUFU instead of 3
    float dd = conf ? (c.x - c.y) : (c.y - c.x);
    float lc = fmaxf(dd, 0.f) + __logf(1.f + __expf(-fabsf(dd)));
    bool pos = conf > 0;

    g_lcneg[gid] = pos ? -1.0f : lc;

    float ll = 0.f;
    float plc = pos ? lc : 0.f;
    if (pos) {
        float4 pr = reinterpret_cast<const float4*>(priors)[p];
        const float* t = targets + (b * OO + idx) * 5;
        float tx0 = t[0], ty0 = t[1], tx1 = t[2], ty1 = t[3];
        float gcx = ((tx0 + tx1) * 0.5f - pr.x) / (0.1f * pr.z);
        float gcy = ((ty0 + ty1) * 0.5f - pr.y) / (0.1f * pr.w);
        float gw = __logf((tx1 - tx0) / pr.z) * 5.0f; // /VAR[1]=0.2
        float gh = __logf((ty1 - ty0) / pr.w) * 5.0f;
        float4 l = reinterpret_cast<const float4*>(arm_loc)[gid];
        float d, ad;
        d = l.x - gcx; ad = fabsf(d); ll += (ad < 1.f) ? 0.5f * d * d : ad - 0.5f;
        d = l.y - gcy; ad = fabsf(d); ll += (ad < 1.f) ? 0.5f * d * d : ad - 0.5f;
        d = l.z - gw;  ad = fabsf(d); ll += (ad < 1.f) ? 0.5f * d * d : ad - 0.5f;
        d = l.w - gh;  ad = fabsf(d); ll += (ad < 1.f) ? 0.5f * d * d : ad - 0.5f;
    }

    // deterministic block reduction (fixed tree)
    for (int o = 16; o > 0; o >>= 1) {
        ll  += __shfl_down_sync(0xFFFFFFFFu, ll, o);
        plc += __shfl_down_sync(0xFFFFFFFFu, plc, o);
    }
    int pc = __popc(__ballot_sync(0xFFFFFFFFu, pos));

    __shared__ float s_ll[8], s_plc[8];
    __shared__ int s_pc[8];
    int lane = threadIdx.x & 31, w = threadIdx.x >> 5;
    if (lane == 0) { s_ll[w] = ll; s_plc[w] = plc; s_pc[w] = pc; }
    __syncthreads();
    if (threadIdx.x == 0) {
        float L = 0.f, Pl = 0.f; int C = 0;
        for (int i = 0; i < 8; i++) { L += s_ll[i]; Pl += s_plc[i]; C += s_pc[i]; }
        g_pll[blockIdx.x] = L;
        g_ppl[blockIdx.x] = Pl;
        g_ppc[blockIdx.x] = C;
    }
}

// ---------------- deterministic partial reduction ----------------
__global__ __launch_bounds__(128) void k_reduce() {
    const int b = blockIdx.x, tid = threadIdx.x;
    int c = g_ppc[b * BLK_PER_B + tid];
    __shared__ int s_c[128];
    s_c[tid] = c;
    __syncthreads();
    for (int o = 64; o > 0; o >>= 1) {
        if (tid < o) s_c[tid] += s_c[tid + o];
        __syncthreads();
    }
    if (tid == 0) g_numpos[b] = s_c[0];

    if (b == 0) {
        float L = 0.f, Pl = 0.f;
        for (int i = tid; i < NBLK_LOSS; i += 128) { L += g_pll[i]; Pl += g_ppl[i]; }
        __shared__ float s_l[128], s_p[128];
        s_l[tid] = L; s_p[tid] = Pl;
        __syncthreads();
        for (int o = 64; o > 0; o >>= 1) {
            if (tid < o) { s_l[tid] += s_l[tid + o]; s_p[tid] += s_p[tid + o]; }
            __syncthreads();
        }
        if (tid == 0) { g_loss_l = s_l[0]; g_loss_c_pos = s_p[0]; }
    }
}

// ---------------- hard-negative mining: exact top-k sum via radix select ----------------
__global__ __launch_bounds__(1024) void k_topk() {
    extern __shared__ float s_lc[]; // PP floats
    __shared__ int s_cnt[256];
    __shared__ float s_rsum[32];
    __shared__ int s_rcnt[32];
    __shared__ unsigned sh_prefix;
    __shared__ int sh_krem, sh_k;

    const int b = blockIdx.x, tid = threadIdx.x, lane = tid & 31, w = tid >> 5;
    const float* src = g_lcneg + b * PP;
    for (int i = tid; i < PP; i += 1024) s_lc[i] = src[i];
    if (tid == 0) {
        long long k = 3ll * (long long)g_numpos[b];
        if (k > PP - 1) k = PP - 1;
        sh_k = (int)k; sh_krem = (int)k; sh_prefix = 0u;
    }
    __syncthreads();

    for (int pass = 0; pass < 4; pass++) {
        const int shift = 24 - 8 * pass;
        if (tid < 256) s_cnt[tid] = 0;
        __syncthreads();
        const unsigned pf = sh_prefix;
        const unsigned himask = (pass == 0) ? 0u : (0xFFFFFFFFu << (shift + 8));
        for (int i = tid; i < PP; i += 1024) {
            float v = s_lc[i];
            unsigned bits = __float_as_uint(v);
            bool ok = (v >= 0.f) && ((bits & himask) == pf);
            int byte = ok ? (int)((bits >> shift) & 255u) : 300;
            unsigned mm = __match_any_sync(0xFFFFFFFFu, byte);
            if (ok && ((__ffs(mm) - 1) == lane)) atomicAdd(&s_cnt[byte], __popc(mm));
        }
        __syncthreads();
        if (tid == 0) {
            if (pass == 0) { // clamp k to number of negative candidates
                int tot = 0;
                for (int j = 0; j < 256; j++) tot += s_cnt[j];
                if (sh_krem > tot) { sh_krem = tot; sh_k = tot; }
            }
            int kr = sh_krem;
            if (kr > 0) {
                int c = 0, sel = 0;
                for (int j = 255; j >= 0; j--) {
                    if (c + s_cnt[j] >= kr) { sel = j; break; }
                    c += s_cnt[j];
                }
                sh_prefix |= ((unsigned)sel) << shift;
                sh_krem = kr - c;
            }
        }
        __syncthreads();
    }

    const float T = __uint_as_float(sh_prefix);
    float sg = 0.f; int cg = 0;
    for (int i = tid; i < PP; i += 1024) {
        float v = s_lc[i];
        if (v > T) { sg += v; cg++; }
    }
    for (int o = 16; o > 0; o >>= 1) {
        sg += __shfl_down_sync(0xFFFFFFFFu, sg, o);
        cg += __shfl_down_sync(0xFFFFFFFFu, cg, o);
    }
    if (lane == 0) { s_rsum[w] = sg; s_rcnt[w] = cg; }
    __syncthreads();
    if (tid == 0) {
        float S = 0.f; int C = 0;
        for (int i = 0; i < 32; i++) { S += s_rsum[i]; C += s_rcnt[i]; }
        g_topk[b] = (sh_k > 0) ? (S + (float)(sh_k - C) * T) : 0.f;
    }
}

// ---------------- finalize (64 threads, fixed tree -> deterministic) ----------------
__global__ void k_final(float* __restrict__ out) {
    const int tid = threadIdx.x; // 64
    __shared__ int s_n[64];
    __shared__ float s_t[64];
    s_n[tid] = g_numpos[tid];
    s_t[tid] = g_topk[tid];
    __syncthreads();
    for (int o = 32; o > 0; o >>= 1) {
        if (tid < o) { s_n[tid] += s_n[tid + o]; s_t[tid] += s_t[tid + o]; }
        __syncthreads();
    }
    if (tid == 0) {
        float fn = (float)s_n[0];
        out[0] = g_loss_l / fn;
        out[1] = (g_loss_c_pos + s_t[0]) / fn;
    }
}

extern "C" void kernel_launch(void* const* d_in, const int* in_sizes, int n_in,
                              void* d_out, int out_size) {
    const float* arm_loc  = (const float*)d_in[0];
    const float* arm_conf = (const float*)d_in[1];
    const float* priors   = (const float*)d_in[4];
    const float* targets  = (const float*)d_in[5];
    float* out = (float*)d_out;

    (void)in_sizes; (void)n_in; (void)out_size;

    static int smem_set = 0;
    if (!smem_set) {
        cudaFuncSetAttribute(k_topk, cudaFuncAttributeMaxDynamicSharedMemorySize, PP * 4);
        smem_set = 1;
    }

    k_init<<<(BB * OO + 255) / 256, 256>>>();
    k_pad<<<1, 32>>>();
    k_pad<<<1, 32>>>();
    k_match<<<dim3(PP / (TPB_A * NPT), BB), TPB_A>>>(priors, targets);
    k_override<<<(BB * OO + 127) / 128, 128>>>(targets);
    k_loss<<<NBLK_LOSS, 256>>>(arm_loc, arm_conf, priors, targets);
    k_reduce<<<BB, 128>>>();
    k_topk<<<BB, 1024, PP * 4>>>();
    k_final<<<1, 64>>>(out);
}

// round 8
// speedup vs baseline: 1.3422x; 1.0217x over previous
#include <cuda_runtime.h>

#define BB 64
#define PP 32768
#define OO 50
#define NPT 4
#define TPB_A 256
#define NBLK_LOSS (BB * PP / 256)   // 8192
#define BLK_PER_B (PP / 256)        // 128

// ---------------- scratch (static device globals; zero-initialized at module load) ----------------
__device__ unsigned long long g_best_packed[BB * OO]; // per (b,truth): (iou_bits<<32)|(~prior)
__device__ int   g_match[BB * PP];                    // normal: (conf<<16)|t ; override: (1<<30)|(j<<16)|lab
__device__ float g_lcneg[BB * PP];                    // lc for negatives, -1 for positives
__device__ float g_pll[NBLK_LOSS];                    // per-block smooth-L1 partials
__device__ float g_ppl[NBLK_LOSS];                    // per-block positive-lc partials
__device__ int   g_ppc[NBLK_LOSS];                    // per-block positive counts
__device__ int   g_numpos[BB];
__device__ float g_topk[BB];

__global__ void k_pad() {} // launch-order shims so ncu capture slot (#4) lands on k_match

// ---------------- match: per-prior best truth + per-truth best prior ----------------
__global__ __launch_bounds__(TPB_A, 4) void k_match(const float* __restrict__ priors,
                                                    const float* __restrict__ targets) {
    const int b = blockIdx.y;
    __shared__ float4 s_box[OO];     // (x0,y0,x1,y1) -> one LDS.128 broadcast per t
    __shared__ float s_area[OO];
    __shared__ int s_lab[OO];
    __shared__ unsigned s_cur[OO];   // float bits of block-best iou per truth (>= 1e-30)

    const int tid = threadIdx.x;
    if (tid < OO) {
        const float* t = targets + (b * OO + tid) * 5;
        float x0 = t[0], y0 = t[1], x1 = t[2], y1 = t[3];
        s_box[tid] = make_float4(x0, y0, x1, y1);
        s_area[tid] = (x1 - x0) * (y1 - y0);
        s_lab[tid] = (t[4] >= 0.f) ? 1 : 0;
        s_cur[tid] = __float_as_uint(1e-30f); // tiny positive: prunes inter==0 for free
    }
    __syncthreads();

    const int pbase = blockIdx.x * (TPB_A * NPT);
    float px0[NPT], py0[NPT], px1[NPT], py1[NPT], pab[NPT];
    float bi[NPT], bu[NPT];
    int   bidx[NPT];
#pragma unroll
    for (int k = 0; k < NPT; k++) {
        int p = pbase + k * TPB_A + tid;
        float4 pr = reinterpret_cast<const float4*>(priors)[p];
        float hw = pr.z * 0.5f, hh = pr.w * 0.5f;
        px0[k] = pr.x - hw; py0[k] = pr.y - hh;
        px1[k] = pr.x + hw; py1[k] = pr.y + hh;
        // match jax: prior area from point-form differences (rounding-faithful)
        pab[k] = (px1[k] - px0[k]) * (py1[k] - py0[k]);
        bi[k] = 0.f; bu[k] = 1.f; bidx[k] = 0;
    }

    const int wid = tid >> 5;
    for (int tt = 0; tt < OO; tt++) {
        int t = tt + wid * 6; if (t >= OO) t -= OO; // rotate start per warp
        const float4 tb = s_box[t];
        const float ta = s_area[t];
        float cur = __uint_as_float(s_cur[t]); // plain LDS; staleness OK (pruning only)
        float slack = -1.f;
#pragma unroll
        for (int k = 0; k < NPT; k++) {
            float w = fminf(px1[k], tb.z) - fmaxf(px0[k], tb.x);
            float h = fminf(py1[k], tb.w) - fmaxf(py0[k], tb.y);
            float inter = fmaxf(w, 0.f) * fmaxf(h, 0.f);
            float uni = (ta + pab[k]) - inter;
            // per-prior best truth (cross-mult, strict >; first-seen wins on tie)
            if (inter * bu[k] > bi[k] * uni) {
                bi[k] = inter; bu[k] = uni; bidx[k] = t;
            }
            // prefilter accumulation only (no branch, no vote per pair)
            slack = fmaxf(slack, fmaf(-cur, uni, inter)); // >=0 iff inter >= cur*uni
        }
        // per-truth best prior: rare, warp-uniform slow path (once per t)
        if (__any_sync(0xFFFFFFFFu, slack >= 0.f)) {
            unsigned long long key = 0ull;
#pragma unroll
            for (int k = 0; k < NPT; k++) {
                float w = fminf(px1[k], tb.z) - fmaxf(px0[k], tb.x);
                float h = fminf(py1[k], tb.w) - fmaxf(py0[k], tb.y);
                float inter = fmaxf(w, 0.f) * fmaxf(h, 0.f);
                float uni = (ta + pab[k]) - inter;
                if (inter >= cur * uni) {
                    float iou = inter / uni; // IEEE div, matches ref exactly
                    unsigned long long kk =
                        ((unsigned long long)__float_as_uint(iou) << 32)
                        | (unsigned)(~(pbase + k * TPB_A + tid)); // tiebreak: lowest prior
                    if (kk > key) key = kk;
                }
            }
#pragma unroll
            for (int o = 16; o > 0; o >>= 1) {
                unsigned long long other = __shfl_xor_sync(0xFFFFFFFFu, key, o);
                if (other > key) key = other;
            }
            if ((tid & 31) == 0 && key != 0ull) {
                atomicMax(&s_cur[t], (unsigned)(key >> 32));
                atomicMax(&g_best_packed[b * OO + t], key); // int max: order-invariant
            }
        }
    }

#pragma unroll
    for (int k = 0; k < NPT; k++) {
        int conf = (2.f * bi[k] >= bu[k]) ? s_lab[bidx[k]] : 0; // iou >= 0.5 (bi>0 implied)
        g_match[b * PP + pbase + k * TPB_A + tid] = (conf << 16) | bidx[k];
    }
}

// ---------------- override: force each truth's best prior (last-j-wins) + reset scratch --------
__global__ void k_override(const float* __restrict__ targets) {
    int i = blockIdx.x * blockDim.x + threadIdx.x;
    if (i >= BB * OO) return;
    int b = i / OO, j = i - b * OO;
    unsigned long long pk = g_best_packed[i];
    g_best_packed[i] = 0ull; // restore zero invariant for next graph replay
    int p = (pk == 0ull) ? 0 : (int)(~(unsigned)(pk & 0xFFFFFFFFull));
    int lab = (targets[i * 5 + 4] >= 0.f) ? 1 : 0;
    // bit30 tag beats any normal match; among overrides larger j wins (= last-j-wins)
    atomicMax(&g_match[b * PP + p], (1 << 30) | (j << 16) | lab);
}

// ---------------- per-prior losses: lc, smooth-L1 on positives, block partials ----------------
__global__ __launch_bounds__(256) void k_loss(const float* __restrict__ arm_loc,
                                              const float* __restrict__ arm_conf,
                                              const float* __restrict__ priors,
                                              const float* __restrict__ targets) {
    const int gid = blockIdx.x * 256 + threadIdx.x;
    const int b = gid >> 15;
    const int p = gid & (PP - 1);

    const int m = g_match[gid];
    int conf, idx;
    if (m & (1 << 30)) { idx = (m >> 16) & 0x3FFF; conf = m & 1; }
    else               { conf = m >> 16;           idx = m & 0xFFFF; }

    float2 c = reinterpret_cast<const float2*>(arm_conf)[gid];
    // lse - picked = softplus(other - picked): 2 MUFU instead of 3
    float dd = conf ? (c.x - c.y) : (c.y - c.x);
    float lc = fmaxf(dd, 0.f) + __logf(1.f + __expf(-fabsf(dd)));
    bool pos = conf > 0;

    g_lcneg[gid] = pos ? -1.0f : lc;

    float ll = 0.f;
    float plc = pos ? lc : 0.f;
    if (pos) {
        float4 pr = reinterpret_cast<const float4*>(priors)[p];
        const float* t = targets + (b * OO + idx) * 5;
        float tx0 = t[0], ty0 = t[1], tx1 = t[2], ty1 = t[3];
        float gcx = ((tx0 + tx1) * 0.5f - pr.x) / (0.1f * pr.z);
        float gcy = ((ty0 + ty1) * 0.5f - pr.y) / (0.1f * pr.w);
        float gw = __logf((tx1 - tx0) / pr.z) * 5.0f; // /VAR[1]=0.2
        float gh = __logf((ty1 - ty0) / pr.w) * 5.0f;
        float4 l = reinterpret_cast<const float4*>(arm_loc)[gid];
        float d, ad;
        d = l.x - gcx; ad = fabsf(d); ll += (ad < 1.f) ? 0.5f * d * d : ad - 0.5f;
        d = l.y - gcy; ad = fabsf(d); ll += (ad < 1.f) ? 0.5f * d * d : ad - 0.5f;
        d = l.z - gw;  ad = fabsf(d); ll += (ad < 1.f) ? 0.5f * d * d : ad - 0.5f;
        d = l.w - gh;  ad = fabsf(d); ll += (ad < 1.f) ? 0.5f * d * d : ad - 0.5f;
    }

    // deterministic block reduction (fixed tree)
    for (int o = 16; o > 0; o >>= 1) {
        ll  += __shfl_down_sync(0xFFFFFFFFu, ll, o);
        plc += __shfl_down_sync(0xFFFFFFFFu, plc, o);
    }
    int pc = __popc(__ballot_sync(0xFFFFFFFFu, pos));

    __shared__ float s_ll[8], s_plc[8];
    __shared__ int s_pc[8];
    int lane = threadIdx.x & 31, w = threadIdx.x >> 5;
    if (lane == 0) { s_ll[w] = ll; s_plc[w] = plc; s_pc[w] = pc; }
    __syncthreads();
    if (threadIdx.x == 0) {
        float L = 0.f, Pl = 0.f; int C = 0;
        for (int i = 0; i < 8; i++) { L += s_ll[i]; Pl += s_plc[i]; C += s_pc[i]; }
        g_pll[blockIdx.x] = L;
        g_ppl[blockIdx.x] = Pl;
        g_ppc[blockIdx.x] = C;
    }
}

// ---------------- hard-negative mining: numpos + exact top-k sum via radix select ----------------
__global__ __launch_bounds__(1024) void k_topk() {
    extern __shared__ float s_lc[]; // PP floats
    __shared__ int s_cnt[256];
    __shared__ float s_rsum[32];
    __shared__ int s_rcnt[32];
    __shared__ int s_np[128];
    __shared__ unsigned sh_prefix;
    __shared__ int sh_krem, sh_k;

    const int b = blockIdx.x, tid = threadIdx.x, lane = tid & 31, w = tid >> 5;
    const float* src = g_lcneg + b * PP;
    for (int i = tid; i < PP; i += 1024) s_lc[i] = src[i];

    // per-batch numpos from this batch's 128 loss-block partials (fixed tree)
    if (tid < 128) s_np[tid] = g_ppc[b * BLK_PER_B + tid];
    __syncthreads();
    if (tid < 64) s_np[tid] += s_np[tid + 64];
    __syncthreads();
    if (tid < 32) {
        int v = s_np[tid] + s_np[tid + 32];
        for (int o = 16; o > 0; o >>= 1) v += __shfl_down_sync(0xFFFFFFFFu, v, o);
        if (tid == 0) {
            g_numpos[b] = v;
            long long k = 3ll * (long long)v;
            if (k > PP - 1) k = PP - 1;
            sh_k = (int)k; sh_krem = (int)k; sh_prefix = 0u;
        }
    }
    __syncthreads();

    for (int pass = 0; pass < 4; pass++) {
        const int shift = 24 - 8 * pass;
        if (tid < 256) s_cnt[tid] = 0;
        __syncthreads();
        const unsigned pf = sh_prefix;
        const unsigned himask = (pass == 0) ? 0u : (0xFFFFFFFFu << (shift + 8));
        for (int i = tid; i < PP; i += 1024) {
            float v = s_lc[i];
            unsigned bits = __float_as_uint(v);
            bool ok = (v >= 0.f) && ((bits & himask) == pf);
            int byte = ok ? (int)((bits >> shift) & 255u) : 300;
            unsigned mm = __match_any_sync(0xFFFFFFFFu, byte);
            if (ok && ((__ffs(mm) - 1) == lane)) atomicAdd(&s_cnt[byte], __popc(mm));
        }
        __syncthreads();
        if (tid == 0) {
            if (pass == 0) { // clamp k to number of negative candidates
                int tot = 0;
                for (int j = 0; j < 256; j++) tot += s_cnt[j];
                if (sh_krem > tot) { sh_krem = tot; sh_k = tot; }
            }
            int kr = sh_krem;
            if (kr > 0) {
                int c = 0, sel = 0;
                for (int j = 255; j >= 0; j--) {
                    if (c + s_cnt[j] >= kr) { sel = j; break; }
                    c += s_cnt[j];
                }
                sh_prefix |= ((unsigned)sel) << shift;
                sh_krem = kr - c;
            }
        }
        __syncthreads();
    }

    const float T = __uint_as_float(sh_prefix);
    float sg = 0.f; int cg = 0;
    for (int i = tid; i < PP; i += 1024) {
        float v = s_lc[i];
        if (v > T) { sg += v; cg++; }
    }
    for (int o = 16; o > 0; o >>= 1) {
        sg += __shfl_down_sync(0xFFFFFFFFu, sg, o);
        cg += __shfl_down_sync(0xFFFFFFFFu, cg, o);
    }
    if (lane == 0) { s_rsum[w] = sg; s_rcnt[w] = cg; }
    __syncthreads();
    if (tid == 0) {
        float S = 0.f; int C = 0;
        for (int i = 0; i < 32; i++) { S += s_rsum[i]; C += s_rcnt[i]; }
        g_topk[b] = (sh_k > 0) ? (S + (float)(sh_k - C) * T) : 0.f;
    }
}

// ---------------- finalize (128 threads, fixed order/trees -> deterministic) ----------------
__global__ __launch_bounds__(128) void k_final(float* __restrict__ out) {
    const int tid = threadIdx.x;
    float L = 0.f, Pl = 0.f;
    for (int i = tid; i < NBLK_LOSS; i += 128) { L += g_pll[i]; Pl += g_ppl[i]; }
    int n = 0; float tk = 0.f;
    if (tid < BB) { n = g_numpos[tid]; tk = g_topk[tid]; }
    __shared__ float s_l[128], s_p[128], s_t[128];
    __shared__ int s_n[128];
    s_l[tid] = L; s_p[tid] = Pl; s_t[tid] = tk; s_n[tid] = n;
    __syncthreads();
    for (int o = 64; o > 0; o >>= 1) {
        if (tid < o) {
            s_l[tid] += s_l[tid + o]; s_p[tid] += s_p[tid + o];
            s_t[tid] += s_t[tid + o]; s_n[tid] += s_n[tid + o];
        }
        __syncthreads();
    }
    if (tid == 0) {
        float fn = (float)s_n[0];
        out[0] = s_l[0] / fn;
        out[1] = (s_p[0] + s_t[0]) / fn;
    }
}

extern "C" void kernel_launch(void* const* d_in, const int* in_sizes, int n_in,
                              void* d_out, int out_size) {
    const float* arm_loc  = (const float*)d_in[0];
    const float* arm_conf = (const float*)d_in[1];
    const float* priors   = (const float*)d_in[4];
    const float* targets  = (const float*)d_in[5];
    float* out = (float*)d_out;

    (void)in_sizes; (void)n_in; (void)out_size;

    static int smem_set = 0;
    if (!smem_set) {
        cudaFuncSetAttribute(k_topk, cudaFuncAttributeMaxDynamicSharedMemorySize, PP * 4);
        smem_set = 1;
    }

    k_pad<<<1, 32>>>();
    k_pad<<<1, 32>>>();
    k_pad<<<1, 32>>>();
    k_match<<<dim3(PP / (TPB_A * NPT), BB), TPB_A>>>(priors, targets);
    k_override<<<(BB * OO + 127) / 128, 128>>>(targets);
    k_loss<<<NBLK_LOSS, 256>>>(arm_loc, arm_conf, priors, targets);
    k_topk<<<BB, 1024, PP * 4>>>();
    k_final<<<1, 128>>>(out);
}

// round 9
// speedup vs baseline: 1.3711x; 1.0215x over previous
#include <cuda_runtime.h>

#define BB 64
#define PP 32768
#define OO 50
#define NPT 4
#define TPB_A 256

// ---------------- scratch (static device globals; zero-initialized at module load) ----------------
__device__ unsigned long long g_best_packed[BB * OO]; // per (b,truth): (iou_bits<<32)|(~prior)
__device__ int   g_match[BB * PP];                    // normal: (conf<<16)|t ; override: (1<<30)|(j<<16)|lab
__device__ float g_pll[BB];                           // per-batch smooth-L1 sums
__device__ float g_ppl[BB];                           // per-batch positive-lc sums
__device__ int   g_numpos[BB];
__device__ float g_topk[BB];

__global__ void k_pad() {} // launch-order shim: puts k_mine at capture slot #4

// slow path for one truth: recompute candidates, warp-reduce packed key, one atomic
#define SLOW_TRUTH(T, TB, TA, CUR)                                                 \
  {                                                                                \
    unsigned long long key = 0ull;                                                 \
    _Pragma("unroll")                                                              \
    for (int k = 0; k < NPT; k++) {                                                \
      float w_ = fminf(px1[k], (TB).z) - fmaxf(px0[k], (TB).x);                    \
      float h_ = fminf(py1[k], (TB).w) - fmaxf(py0[k], (TB).y);                    \
      float in_ = fmaxf(w_, 0.f) * fmaxf(h_, 0.f);                                 \
      float un_ = ((TA) + pab[k]) - in_;                                           \
      if (in_ >= (CUR) * un_) {                                                    \
        float iou_ = in_ / un_; /* IEEE div, matches ref exactly */                 \
        unsigned long long kk = ((unsigned long long)__float_as_uint(iou_) << 32)  \
                              | (unsigned)(~(pbase + k * TPB_A + tid));            \
        if (kk > key) key = kk;                                                    \
      }                                                                            \
    }                                                                              \
    _Pragma("unroll")                                                              \
    for (int o_ = 16; o_ > 0; o_ >>= 1) {                                          \
      unsigned long long other_ = __shfl_xor_sync(0xFFFFFFFFu, key, o_);           \
      if (other_ > key) key = other_;                                              \
    }                                                                              \
    if ((tid & 31) == 0 && key != 0ull) {                                          \
      atomicMax(&s_cur[(T)], (unsigned)(key >> 32));                               \
      atomicMax(&g_best_packed[b * OO + (T)], key); /* int max: order-invariant */ \
    }                                                                              \
  }

// ---------------- match: per-prior best truth + per-truth best prior ----------------
__global__ __launch_bounds__(TPB_A, 3) void k_match(const float* __restrict__ priors,
                                                    const float* __restrict__ targets) {
    const int b = blockIdx.y;
    __shared__ float4 s_box[OO];     // (x0,y0,x1,y1) -> one LDS.128 broadcast per t
    __shared__ float s_area[OO];
    __shared__ int s_lab[OO];
    __shared__ unsigned s_cur[OO];   // float bits of block-best iou per truth (>= 1e-30)

    const int tid = threadIdx.x;
    if (tid < OO) {
        const float* t = targets + (b * OO + tid) * 5;
        float x0 = t[0], y0 = t[1], x1 = t[2], y1 = t[3];
        s_box[tid] = make_float4(x0, y0, x1, y1);
        s_area[tid] = (x1 - x0) * (y1 - y0);
        s_lab[tid] = (t[4] >= 0.f) ? 1 : 0;
        s_cur[tid] = __float_as_uint(1e-30f); // tiny positive: prunes inter==0 for free
    }
    __syncthreads();

    const int pbase = blockIdx.x * (TPB_A * NPT);
    float px0[NPT], py0[NPT], px1[NPT], py1[NPT], pab[NPT];
    float bi[NPT], bu[NPT];
    int   bidx[NPT];
#pragma unroll
    for (int k = 0; k < NPT; k++) {
        int p = pbase + k * TPB_A + tid;
        float4 pr = reinterpret_cast<const float4*>(priors)[p];
        float hw = pr.z * 0.5f, hh = pr.w * 0.5f;
        px0[k] = pr.x - hw; py0[k] = pr.y - hh;
        px1[k] = pr.x + hw; py1[k] = pr.y + hh;
        // match jax: prior area from point-form differences (rounding-faithful)
        pab[k] = (px1[k] - px0[k]) * (py1[k] - py0[k]);
        bi[k] = 0.f; bu[k] = 1.f; bidx[k] = 0;
    }

    const int wid = tid >> 5;
    // OO=50: tt even, wid*6 even -> t0 even in [0,48], t1=t0+1 odd, no wrap needed
    for (int tt = 0; tt < OO; tt += 2) {
        int t0 = tt + wid * 6; if (t0 >= OO) t0 -= OO;
        const int t1 = t0 + 1;
        const float4 tb0 = s_box[t0];
        const float4 tb1 = s_box[t1];
        const float ta0 = s_area[t0], ta1 = s_area[t1];
        float cur0 = __uint_as_float(s_cur[t0]); // plain LDS; staleness OK (pruning only)
        float cur1 = __uint_as_float(s_cur[t1]);
        float slack = -1.f;
#pragma unroll
        for (int k = 0; k < NPT; k++) {
            // truth t0
            float w0 = fminf(px1[k], tb0.z) - fmaxf(px0[k], tb0.x);
            float h0 = fminf(py1[k], tb0.w) - fmaxf(py0[k], tb0.y);
            float i0 = fmaxf(w0, 0.f) * fmaxf(h0, 0.f);
            float u0 = (ta0 + pab[k]) - i0;
            if (i0 * bu[k] > bi[k] * u0) { bi[k] = i0; bu[k] = u0; bidx[k] = t0; }
            slack = fmaxf(slack, fmaf(-cur0, u0, i0)); // >=0 iff i0 >= cur0*u0
            // truth t1
            float w1 = fminf(px1[k], tb1.z) - fmaxf(px0[k], tb1.x);
            float h1 = fminf(py1[k], tb1.w) - fmaxf(py0[k], tb1.y);
            float i1 = fmaxf(w1, 0.f) * fmaxf(h1, 0.f);
            float u1 = (ta1 + pab[k]) - i1;
            if (i1 * bu[k] > bi[k] * u1) { bi[k] = i1; bu[k] = u1; bidx[k] = t1; }
            slack = fmaxf(slack, fmaf(-cur1, u1, i1));
        }
        // rare warp-uniform slow path: one vote + branch per TWO truths
        if (__any_sync(0xFFFFFFFFu, slack >= 0.f)) {
            SLOW_TRUTH(t0, tb0, ta0, cur0)
            SLOW_TRUTH(t1, tb1, ta1, cur1)
        }
    }

#pragma unroll
    for (int k = 0; k < NPT; k++) {
        int conf = (2.f * bi[k] >= bu[k]) ? s_lab[bidx[k]] : 0; // iou >= 0.5 (bi>0 implied)
        g_match[b * PP + pbase + k * TPB_A + tid] = (conf << 16) | bidx[k];
    }
}

// ---------------- override: force each truth's best prior (last-j-wins) + reset scratch --------
__global__ void k_override(const float* __restrict__ targets) {
    int i = blockIdx.x * blockDim.x + threadIdx.x;
    if (i >= BB * OO) return;
    int b = i / OO, j = i - b * OO;
    unsigned long long pk = g_best_packed[i];
    g_best_packed[i] = 0ull; // restore zero invariant for next graph replay
    int p = (pk == 0ull) ? 0 : (int)(~(unsigned)(pk & 0xFFFFFFFFull));
    int lab = (targets[i * 5 + 4] >= 0.f) ? 1 : 0;
    // bit30 tag beats any normal match; among overrides larger j wins (= last-j-wins)
    atomicMax(&g_match[b * PP + p], (1 << 30) | (j << 16) | lab);
}

// ---------------- fused per-batch: losses + numpos + hard-negative top-k (radix select) --------
__global__ __launch_bounds__(1024) void k_mine(const float* __restrict__ arm_loc,
                                               const float* __restrict__ arm_conf,
                                               const float* __restrict__ priors,
                                               const float* __restrict__ targets) {
    extern __shared__ float s_lc[]; // PP floats (128KB)
    __shared__ int s_cnt[256];
    __shared__ float s_rf[32], s_rf2[32];
    __shared__ int s_ri[32], s_ri2[32];
    __shared__ unsigned sh_prefix;
    __shared__ int sh_krem, sh_k;

    const int b = blockIdx.x, tid = threadIdx.x, lane = tid & 31, w = tid >> 5;

    // ---- phase 1: per-prior loss terms ----
    float ll = 0.f, plc = 0.f; int pc = 0;
    for (int i = tid; i < PP; i += 1024) {
        const int gid = (b << 15) + i;
        const int m = g_match[gid];
        int conf, idx;
        if (m & (1 << 30)) { idx = (m >> 16) & 0x3FFF; conf = m & 1; }
        else               { conf = m >> 16;           idx = m & 0xFFFF; }

        float2 c = reinterpret_cast<const float2*>(arm_conf)[gid];
        float dd = conf ? (c.x - c.y) : (c.y - c.x);
        float lc = fmaxf(dd, 0.f) + __logf(1.f + __expf(-fabsf(dd))); // lse - picked
        bool pos = conf > 0;
        s_lc[i] = pos ? -1.0f : lc;
        if (pos) {
            pc++; plc += lc;
            float4 pr = reinterpret_cast<const float4*>(priors)[i];
            const float* t = targets + (b * OO + idx) * 5;
            float tx0 = t[0], ty0 = t[1], tx1 = t[2], ty1 = t[3];
            float gcx = ((tx0 + tx1) * 0.5f - pr.x) / (0.1f * pr.z);
            float gcy = ((ty0 + ty1) * 0.5f - pr.y) / (0.1f * pr.w);
            float gw = __logf((tx1 - tx0) / pr.z) * 5.0f; // /VAR[1]=0.2
            float gh = __logf((ty1 - ty0) / pr.w) * 5.0f;
            float4 l = reinterpret_cast<const float4*>(arm_loc)[gid];
            float d, ad;
            d = l.x - gcx; ad = fabsf(d); ll += (ad < 1.f) ? 0.5f * d * d : ad - 0.5f;
            d = l.y - gcy; ad = fabsf(d); ll += (ad < 1.f) ? 0.5f * d * d : ad - 0.5f;
            d = l.z - gw;  ad = fabsf(d); ll += (ad < 1.f) ? 0.5f * d * d : ad - 0.5f;
            d = l.w - gh;  ad = fabsf(d); ll += (ad < 1.f) ? 0.5f * d * d : ad - 0.5f;
        }
    }
    // fixed-tree block reduction of (ll, plc, pc)
    for (int o = 16; o > 0; o >>= 1) {
        ll  += __shfl_down_sync(0xFFFFFFFFu, ll, o);
        plc += __shfl_down_sync(0xFFFFFFFFu, plc, o);
        pc  += __shfl_down_sync(0xFFFFFFFFu, pc, o);
    }
    if (lane == 0) { s_rf[w] = ll; s_rf2[w] = plc; s_ri[w] = pc; }
    __syncthreads();
    if (tid == 0) {
        float L = 0.f, Pl = 0.f; int n = 0;
        for (int i = 0; i < 32; i++) { L += s_rf[i]; Pl += s_rf2[i]; n += s_ri[i]; }
        g_pll[b] = L; g_ppl[b] = Pl; g_numpos[b] = n;
        long long k = 3ll * (long long)n;
        if (k > PP - 1) k = PP - 1;
        sh_k = (int)k; sh_krem = (int)k; sh_prefix = 0u;
    }
    __syncthreads();

    // ---- phase 2: 4-pass radix select over negative lc values ----
    for (int pass = 0; pass < 4; pass++) {
        const int shift = 24 - 8 * pass;
        if (tid < 256) s_cnt[tid] = 0;
        __syncthreads();
        const unsigned pf = sh_prefix;
        const unsigned himask = (pass == 0) ? 0u : (0xFFFFFFFFu << (shift + 8));
        for (int i = tid; i < PP; i += 1024) {
            float v = s_lc[i];
            unsigned bits = __float_as_uint(v);
            bool ok = (v >= 0.f) && ((bits & himask) == pf);
            int byte = ok ? (int)((bits >> shift) & 255u) : 300;
            unsigned mm = __match_any_sync(0xFFFFFFFFu, byte);
            if (ok && ((__ffs(mm) - 1) == lane)) atomicAdd(&s_cnt[byte], __popc(mm));
        }
        __syncthreads();
        // warp-parallel descending suffix scan: lane L owns buckets 255-8L .. 248-8L
        if (tid < 32) {
            int base = 255 - 8 * lane;
            int s = 0;
#pragma unroll
            for (int d = 0; d < 8; d++) s += s_cnt[base - d];
            int incl = s;
#pragma unroll
            for (int o = 1; o < 32; o <<= 1) {
                int v = __shfl_up_sync(0xFFFFFFFFu, incl, o);
                if (lane >= o) incl += v;
            }
            int excl = incl - s;
            int tot = __shfl_sync(0xFFFFFFFFu, incl, 31);
            int kr = sh_krem;
            int kr_eff = (pass == 0 && kr > tot) ? tot : kr;
            if (pass == 0 && lane == 0) { sh_k = kr_eff; sh_krem = kr_eff; }
            if (kr_eff > 0 && excl < kr_eff && kr_eff <= incl) {
                int c = excl;
#pragma unroll
                for (int d = 0; d < 8; d++) {
                    int j = base - d;
                    int cj = s_cnt[j];
                    if (c + cj >= kr_eff) {
                        sh_prefix = pf | (((unsigned)j) << shift);
                        sh_krem = kr_eff - c;
                        break;
                    }
                    c += cj;
                }
            }
        }
        __syncthreads();
    }

    // ---- phase 3: sum strictly-above-threshold + tie remainder ----
    const float T = __uint_as_float(sh_prefix);
    float sg = 0.f; int cg = 0;
    for (int i = tid; i < PP; i += 1024) {
        float v = s_lc[i];
        if (v > T) { sg += v; cg++; }
    }
    for (int o = 16; o > 0; o >>= 1) {
        sg += __shfl_down_sync(0xFFFFFFFFu, sg, o);
        cg += __shfl_down_sync(0xFFFFFFFFu, cg, o);
    }
    if (lane == 0) { s_rf[w] = sg; s_ri[w] = cg; }
    __syncthreads();
    if (tid == 0) {
        float S = 0.f; int C = 0;
        for (int i = 0; i < 32; i++) { S += s_rf[i]; C += s_ri[i]; }
        g_topk[b] = (sh_k > 0) ? (S + (float)(sh_k - C) * T) : 0.f;
    }
}

// ---------------- finalize (64 threads, fixed trees -> deterministic) ----------------
__global__ void k_final(float* __restrict__ out) {
    const int tid = threadIdx.x; // 64
    __shared__ float s_l[64], s_p[64], s_t[64];
    __shared__ int s_n[64];
    s_l[tid] = g_pll[tid]; s_p[tid] = g_ppl[tid];
    s_t[tid] = g_topk[tid]; s_n[tid] = g_numpos[tid];
    __syncthreads();
    for (int o = 32; o > 0; o >>= 1) {
        if (tid < o) {
            s_l[tid] += s_l[tid + o]; s_p[tid] += s_p[tid + o];
            s_t[tid] += s_t[tid + o]; s_n[tid] += s_n[tid + o];
        }
        __syncthreads();
    }
    if (tid == 0) {
        float fn = (float)s_n[0];
        out[0] = s_l[0] / fn;
        out[1] = (s_p[0] + s_t[0]) / fn;
    }
}

extern "C" void kernel_launch(void* const* d_in, const int* in_sizes, int n_in,
                              void* d_out, int out_size) {
    const float* arm_loc  = (const float*)d_in[0];
    const float* arm_conf = (const float*)d_in[1];
    const float* priors   = (const float*)d_in[4];
    const float* targets  = (const float*)d_in[5];
    float* out = (float*)d_out;

    (void)in_sizes; (void)n_in; (void)out_size;

    static int smem_set = 0;
    if (!smem_set) {
        cudaFuncSetAttribute(k_mine, cudaFuncAttributeMaxDynamicSharedMemorySize, PP * 4);
        smem_set = 1;
    }

    k_match<<<dim3(PP / (TPB_A * NPT), BB), TPB_A>>>(priors, targets);
    k_override<<<(BB * OO + 127) / 128, 128>>>(targets);
    k_pad<<<1, 32>>>();
    k_mine<<<BB, 1024, PP * 4>>>(arm_loc, arm_conf, priors, targets);
    k_final<<<1, 64>>>(out);
}